// round 6
// baseline (speedup 1.0000x reference)
#include <cuda_runtime.h>
#include <cuda_fp16.h>
#include <math.h>
#include <stdint.h>

#define BATCH 32
#define C     256
#define COUT  256
#define H     56
#define W     56
#define HW    3136

#define XWORDS 1856          // x buffer: 8 pair-planes x 4 rows x 58 cols
#define WWORDS 9216          // w buffer: 9 taps x 128 couts x 8 words
#define SMEM_BYTES ((2*XWORDS + 2*WWORDS) * 4)   // 88576

// Packed quantized fp16 weights: [chunk(16)][tap(9)][cout(256)][slot(16)]
__device__ unsigned short g_wq[16u * 9u * 256u * 16u];

__device__ __forceinline__ float quant_fixed(float x) {
    float v = floorf(x * 65536.0f) * (1.0f / 65536.0f);
    return fminf(fmaxf(v, -32768.0f), 32767.0f);
}

__device__ __forceinline__ uint32_t smem_u32(const void* p) {
    uint32_t a;
    asm("{ .reg .u64 t; cvta.to.shared.u64 t, %1; cvt.u32.u64 %0, t; }" : "=r"(a) : "l"(p));
    return a;
}
#define CP_ASYNC16(dst, src) \
    asm volatile("cp.async.cg.shared.global [%0], [%1], 16;" :: "r"(dst), "l"(src))
#define CP_COMMIT()  asm volatile("cp.async.commit_group;" ::: "memory")
#define CP_WAIT0()   asm volatile("cp.async.wait_group 0;" ::: "memory")

// ---------------- weight pre-quantization / packing ----------------
__global__ void quant_weights_kernel(const float* __restrict__ shiftp,
                                     const float* __restrict__ signp)
{
    int gid = blockIdx.x * blockDim.x + threadIdx.x;   // [cout][ci][tap]
    int cout = gid / (C * 9);
    int rem  = gid - cout * (C * 9);
    int ci   = rem / 9;
    int tap  = rem - ci * 9;

    float sr = rintf(fminf(fmaxf(shiftp[gid], -14.0f), 0.0f));
    float g  = rintf(signp[gid]);
    float sg = (g > 0.0f) ? 1.0f : ((g < 0.0f) ? -1.0f : 0.0f);
    float wf = ldexpf(sg, (int)sr);
    __half h = __float2half(wf);                       // exact

    int chunk = ci >> 4;
    int l     = ci & 15;
    int slot  = ((l >> 1) & 3) * 4 + (l >> 3) * 2 + (l & 1);
    g_wq[(((size_t)(chunk * 9 + tap) * 256 + cout) << 4) + slot] = __half_as_ushort(h);
}

// ---------------- staging helpers ----------------
struct XIter { int idx; float v0, v1; };

__device__ __forceinline__ void x_ldg(XIter& s, int it, int tid, int oh_base,
                                      const float* __restrict__ inc)
{
    s.idx = tid + it * 256;
    int c    = s.idx / 232;
    int rem  = s.idx - c * 232;
    int row  = rem / 58;
    int col  = rem - row * 58;
    int ih = oh_base + row - 1;
    int iw = col - 1;
    bool inb = (s.idx < XWORDS) && (ih >= 0) && (ih < H) && (iw >= 0) && (iw < W);
    s.v0 = 0.0f; s.v1 = 0.0f;
    if (inb) {
        const float* p = inc + (size_t)(2 * c) * HW + ih * W + iw;
        s.v0 = __ldg(p);
        s.v1 = __ldg(p + HW);
    }
}
__device__ __forceinline__ void x_sts(const XIter& s, uint32_t* __restrict__ xd)
{
    if (s.idx < XWORDS) {
        uint32_t h0 = __half_as_ushort(__float2half(quant_fixed(s.v0)));
        uint32_t h1 = __half_as_ushort(__float2half(quant_fixed(s.v1)));
        xd[s.idx] = (h1 << 16) | h0;
    }
}

// ---------------- main MMA conv ----------------
// CTA: M=112 (2 rows), N=128. 8 warps = 2(M:4/3 mt) x 4(N:32 couts).
// 16 ci-chunks x 9 taps, K16 = 16 ci. Double-buffered smem, cp.async weights.

template<int MTS>
__device__ __forceinline__ void conv_body(
    const float* __restrict__ in_b,
    const float* __restrict__ biasp,
    float* __restrict__ out_b,
    uint32_t* __restrict__ smem,
    int oh_base, int cout0, int tid, int wn, int mt0)
{
    uint32_t* sx[2] = { smem, smem + XWORDS };
    uint32_t* sw[2] = { smem + 2 * XWORDS, smem + 2 * XWORDS + WWORDS };
    const uint32_t sw_addr[2] = { smem_u32(sw[0]), smem_u32(sw[1]) };

    const int lane = tid & 31;
    const int qc = lane & 3;
    const int qr = lane >> 2;

    int offA[MTS], offB[MTS];
#pragma unroll
    for (int mt = 0; mt < MTS; ++mt) {
        int mA = (mt0 + mt) * 16 + qr;
        int mB = mA + 8;
        offA[mt] = (mA / 56) * 58 + (mA % 56);
        offB[mt] = (mB / 56) * 58 + (mB % 56);
    }

    float acc[MTS][4][4];
#pragma unroll
    for (int mt = 0; mt < MTS; ++mt)
#pragma unroll
        for (int nn = 0; nn < 4; ++nn)
#pragma unroll
            for (int r = 0; r < 4; ++r) acc[mt][nn][r] = 0.0f;

    const int qc232 = qc * 232;
    // byte pointer at this CTA's cout block (each cout = 32 bytes per (chunk,tap))
    const char* wsrc_base = (const char*)g_wq + ((size_t)cout0 * 32);

    // ---- prologue: stage chunk 0 ----
    {
#pragma unroll
        for (int it = 0; it < 8; ++it) {
            XIter s; x_ldg(s, it, tid, oh_base, in_b); x_sts(s, sx[0]);
        }
#pragma unroll
        for (int tap = 0; tap < 9; ++tap)
            CP_ASYNC16(sw_addr[0] + tap * 4096 + tid * 16,
                       wsrc_base + (size_t)tap * 8192 + tid * 16);
        CP_COMMIT();
    }

    for (int chunk = 0; chunk < 16; ++chunk) {
        const int cur = chunk & 1, nxt = cur ^ 1;
        const bool hasnext = (chunk < 15);
        CP_WAIT0();
        __syncthreads();

        if (hasnext) {
            const char* wsrc = wsrc_base + (size_t)(chunk + 1) * 9 * 8192;
#pragma unroll
            for (int tap = 0; tap < 9; ++tap)
                CP_ASYNC16(sw_addr[nxt] + tap * 4096 + tid * 16,
                           wsrc + (size_t)tap * 8192 + tid * 16);
            CP_COMMIT();
        }

        const float* inc_n = in_b + (size_t)(chunk + 1) * 16 * HW;
        const uint32_t* xc = sx[cur];
        const uint32_t* wc = sw[cur];
        XIter pipe[2];

#pragma unroll
        for (int tap = 0; tap < 9; ++tap) {
            // interleaved staging of next x (2-deep LDG->STS pipeline)
            if (hasnext && tap < 8) {
                if (tap >= 2) x_sts(pipe[tap & 1], sx[nxt]);
                x_ldg(pipe[tap & 1], tap, tid, oh_base, inc_n);
            }

            const int kh = tap / 3, kw = tap - kh * 3;
            const int tadd = kh * 58 + kw;

            uint32_t b0[4], b1[4];
#pragma unroll
            for (int nn = 0; nn < 4; ++nn) {
                int cl = wn * 32 + nn * 8 + qr;
                uint2 bb = *(const uint2*)&wc[tap * 1024 + cl * 8 + 2 * qc];
                b0[nn] = bb.x; b1[nn] = bb.y;
            }
#pragma unroll
            for (int mt = 0; mt < MTS; ++mt) {
                uint32_t a0 = xc[qc232 + tadd + offA[mt]];
                uint32_t a1 = xc[qc232 + tadd + offB[mt]];
                uint32_t a2 = xc[qc232 + 928 + tadd + offA[mt]];
                uint32_t a3 = xc[qc232 + 928 + tadd + offB[mt]];
#pragma unroll
                for (int nn = 0; nn < 4; ++nn) {
                    asm volatile(
                        "mma.sync.aligned.m16n8k16.row.col.f32.f16.f16.f32 "
                        "{%0,%1,%2,%3}, {%4,%5,%6,%7}, {%8,%9}, {%0,%1,%2,%3};\n"
                        : "+f"(acc[mt][nn][0]), "+f"(acc[mt][nn][1]),
                          "+f"(acc[mt][nn][2]), "+f"(acc[mt][nn][3])
                        : "r"(a0), "r"(a1), "r"(a2), "r"(a3),
                          "r"(b0[nn]), "r"(b1[nn]));
                }
            }
        }
        if (hasnext) {   // drain staging pipeline (iters 6, 7)
            x_sts(pipe[0], sx[nxt]);
            x_sts(pipe[1], sx[nxt]);
        }
    }

    // ---- epilogue ----
#pragma unroll
    for (int nn = 0; nn < 4; ++nn) {
        int cl = wn * 32 + nn * 8 + 2 * qc;
        float bq0 = quant_fixed(biasp[cout0 + cl]);
        float bq1 = quant_fixed(biasp[cout0 + cl + 1]);
        float* o0 = out_b + (size_t)(cout0 + cl) * HW;
        float* o1 = o0 + HW;
#pragma unroll
        for (int mt = 0; mt < MTS; ++mt) {
            int mA = (mt0 + mt) * 16 + qr;
            int mB = mA + 8;
            int iA = (oh_base + mA / 56) * W + (mA % 56);
            int iB = (oh_base + mB / 56) * W + (mB % 56);
            o0[iA] = acc[mt][nn][0] + bq0;
            o1[iA] = acc[mt][nn][1] + bq1;
            o0[iB] = acc[mt][nn][2] + bq0;
            o1[iB] = acc[mt][nn][3] + bq1;
        }
    }
}

__global__ __launch_bounds__(256, 2)
void conv_mma_kernel(const float* __restrict__ in,
                     const float* __restrict__ biasp,
                     float* __restrict__ out)
{
    extern __shared__ uint32_t smem[];

    const int tid = threadIdx.x;
    const int w   = tid >> 5;
    const int wm  = w & 1;
    const int wn  = w >> 1;
    const int oh_base = blockIdx.x * 2;
    const int cout0   = blockIdx.y * 128;
    const int b       = blockIdx.z;

    const float* in_b  = in  + (size_t)b * C * HW;
    float*       out_b = out + (size_t)b * COUT * HW;

    if (wm == 0)
        conv_body<4>(in_b, biasp, out_b, smem, oh_base, cout0, tid, wn, 0);
    else
        conv_body<3>(in_b, biasp, out_b, smem, oh_base, cout0, tid, wn, 4);
}

extern "C" void kernel_launch(void* const* d_in, const int* in_sizes, int n_in,
                              void* d_out, int out_size)
{
    const float* in    = (const float*)d_in[0];
    const float* shift = (const float*)d_in[1];
    const float* sign  = (const float*)d_in[2];
    const float* bias  = (const float*)d_in[3];
    float* out = (float*)d_out;

    cudaFuncSetAttribute(conv_mma_kernel,
                         cudaFuncAttributeMaxDynamicSharedMemorySize, SMEM_BYTES);

    quant_weights_kernel<<<2304, 256>>>(shift, sign);
    dim3 grid(H / 2, COUT / 128, BATCH);               // 28 x 2 x 32
    conv_mma_kernel<<<grid, 256, SMEM_BYTES>>>(in, bias, out);
}

// round 7
// speedup vs baseline: 1.8242x; 1.8242x over previous
#include <cuda_runtime.h>
#include <cuda_fp16.h>
#include <math.h>
#include <stdint.h>

#define BATCH 32
#define C     256
#define COUT  256
#define H     56
#define W     56
#define HW    3136

#define XWORDS 1856          // x buffer: 8 pair-planes x 4 rows x 58 cols (stride 232)
#define WWORDS 9216          // w buffer: 9 taps x 128 couts x 8 words
#define SMEM_WORDS (XWORDS + 2 * WWORDS)        // 20288
#define SMEM_BYTES (SMEM_WORDS * 4)             // 81152

// Packed quantized fp16 weights: [chunk(16)][tap(9)][cout(256)][slot(16)]
__device__ unsigned short g_wq[16u * 9u * 256u * 16u];

__device__ __forceinline__ float quant_fixed(float x) {
    float v = floorf(x * 65536.0f) * (1.0f / 65536.0f);
    return fminf(fmaxf(v, -32768.0f), 32767.0f);
}

__device__ __forceinline__ uint32_t smem_u32(const void* p) {
    uint32_t a;
    asm("{ .reg .u64 t; cvta.to.shared.u64 t, %1; cvt.u32.u64 %0, t; }" : "=r"(a) : "l"(p));
    return a;
}
#define CP_ASYNC16(dst, src) \
    asm volatile("cp.async.cg.shared.global [%0], [%1], 16;" :: "r"(dst), "l"(src))
#define CP_COMMIT()  asm volatile("cp.async.commit_group;" ::: "memory")
#define CP_WAIT0()   asm volatile("cp.async.wait_group 0;" ::: "memory")

// ---------------- weight pre-quantization / packing ----------------
__global__ void quant_weights_kernel(const float* __restrict__ shiftp,
                                     const float* __restrict__ signp)
{
    int gid = blockIdx.x * blockDim.x + threadIdx.x;   // [cout][ci][tap]
    int cout = gid / (C * 9);
    int rem  = gid - cout * (C * 9);
    int ci   = rem / 9;
    int tap  = rem - ci * 9;

    float sr = rintf(fminf(fmaxf(shiftp[gid], -14.0f), 0.0f));
    float g  = rintf(signp[gid]);
    float sg = (g > 0.0f) ? 1.0f : ((g < 0.0f) ? -1.0f : 0.0f);
    float wf = ldexpf(sg, (int)sr);
    __half h = __float2half(wf);                       // exact

    int chunk = ci >> 4;
    int l     = ci & 15;
    int slot  = ((l >> 1) & 3) * 4 + (l >> 3) * 2 + (l & 1);
    g_wq[(((size_t)(chunk * 9 + tap) * 256 + cout) << 4) + slot] = __half_as_ushort(h);
}

// ---------------- main MMA conv ----------------
// CTA: M=112 (2 rows), N=128. 8 warps = 2(M: 4/3 mtiles) x 4(N: 32 couts).
// 16 ci-chunks x 9 taps, K16 = 16 ci.
// Weights: cp.async double-buffered. x: register prefetch issued before MMA loop,
// STS after post-MMA barrier. MMA tap loop contains NOTHING else (R4-identical).

template<int MTS>
__device__ __forceinline__ void conv_body(
    const float* __restrict__ in_b,
    const float* __restrict__ biasp,
    float* __restrict__ out_b,
    uint32_t* __restrict__ smem,
    int oh_base, int cout0, int tid, int wn, int mt0)
{
    uint32_t* sx    = smem;
    uint32_t* sw[2] = { smem + XWORDS, smem + XWORDS + WWORDS };
    const uint32_t sw_addr[2] = { smem_u32(sw[0]), smem_u32(sw[1]) };

    const int lane = tid & 31;
    const int qc = lane & 3;
    const int qr = lane >> 2;

    int offA[MTS], offB[MTS];
#pragma unroll
    for (int mt = 0; mt < MTS; ++mt) {
        int mA = (mt0 + mt) * 16 + qr;
        int mB = mA + 8;
        offA[mt] = (mA / 56) * 58 + (mA % 56);
        offB[mt] = (mB / 56) * 58 + (mB % 56);
    }

    float acc[MTS][4][4];
#pragma unroll
    for (int mt = 0; mt < MTS; ++mt)
#pragma unroll
        for (int nn = 0; nn < 4; ++nn)
#pragma unroll
            for (int r = 0; r < 4; ++r) acc[mt][nn][r] = 0.0f;

    const int qc232 = qc * 232;
    const char* wsrc_base = (const char*)g_wq + ((size_t)cout0 * 32);

    // ---- precompute chunk-invariant x staging geometry (8 slots/thread) ----
    int  xoff[8];     // word offset within 16-plane group: 2*c*HW + ih*W + iw
    bool xval[8];
#pragma unroll
    for (int it = 0; it < 8; ++it) {
        int idx  = tid + it * 256;
        int c    = idx / 232;
        int rem  = idx - c * 232;
        int row  = rem / 58;
        int col  = rem - row * 58;
        int ih   = oh_base + row - 1;
        int iw   = col - 1;
        xval[it] = (idx < XWORDS) && (ih >= 0) && (ih < H) && (iw >= 0) && (iw < W);
        xoff[it] = 2 * c * HW + ih * W + iw;
    }

    // ---- prologue: stage x chunk 0, launch weights chunk 0 ----
#pragma unroll
    for (int it = 0; it < 8; ++it) {
        int idx = tid + it * 256;
        if (idx < XWORDS) {
            float v0 = 0.0f, v1 = 0.0f;
            if (xval[it]) {
                const float* p = in_b + xoff[it];
                v0 = __ldg(p); v1 = __ldg(p + HW);
            }
            uint32_t h0 = __half_as_ushort(__float2half(quant_fixed(v0)));
            uint32_t h1 = __half_as_ushort(__float2half(quant_fixed(v1)));
            sx[idx] = (h1 << 16) | h0;
        }
    }
#pragma unroll
    for (int tap = 0; tap < 9; ++tap)
        CP_ASYNC16(sw_addr[0] + tap * 4096 + tid * 16,
                   wsrc_base + (size_t)tap * 8192 + tid * 16);
    CP_COMMIT();

    for (int chunk = 0; chunk < 16; ++chunk) {
        const int cur = chunk & 1, nxt = cur ^ 1;
        const bool hasnext = (chunk < 15);

        CP_WAIT0();
        __syncthreads();   // weights[cur] ready; prev STS x visible; sw[nxt] free

        if (hasnext) {
            const char* wsrc = wsrc_base + (size_t)(chunk + 1) * 9 * 8192;
#pragma unroll
            for (int tap = 0; tap < 9; ++tap)
                CP_ASYNC16(sw_addr[nxt] + tap * 4096 + tid * 16,
                           wsrc + (size_t)tap * 8192 + tid * 16);
            CP_COMMIT();
        }

        // front-batched x prefetch for chunk+1 (latency hides under MMA loop)
        float pv0[8], pv1[8];
        if (hasnext) {
            const float* inc_n = in_b + (size_t)(chunk + 1) * 16 * HW;
#pragma unroll
            for (int it = 0; it < 8; ++it) {
                pv0[it] = 0.0f; pv1[it] = 0.0f;
                if (xval[it]) {
                    const float* p = inc_n + xoff[it];
                    pv0[it] = __ldg(p); pv1[it] = __ldg(p + HW);
                }
            }
        }

        const uint32_t* wc = sw[cur];
        // ---- pure MMA tap loop (identical to R4 hot loop) ----
#pragma unroll
        for (int tap = 0; tap < 9; ++tap) {
            const int kh = tap / 3, kw = tap - kh * 3;
            const int tadd = kh * 58 + kw;

            uint32_t b0[4], b1[4];
#pragma unroll
            for (int nn = 0; nn < 4; ++nn) {
                int cl = wn * 32 + nn * 8 + qr;
                uint2 bb = *(const uint2*)&wc[tap * 1024 + cl * 8 + 2 * qc];
                b0[nn] = bb.x; b1[nn] = bb.y;
            }
#pragma unroll
            for (int mt = 0; mt < MTS; ++mt) {
                uint32_t a0 = sx[qc232 + tadd + offA[mt]];
                uint32_t a1 = sx[qc232 + tadd + offB[mt]];
                uint32_t a2 = sx[qc232 + 928 + tadd + offA[mt]];
                uint32_t a3 = sx[qc232 + 928 + tadd + offB[mt]];
#pragma unroll
                for (int nn = 0; nn < 4; ++nn) {
                    asm volatile(
                        "mma.sync.aligned.m16n8k16.row.col.f32.f16.f16.f32 "
                        "{%0,%1,%2,%3}, {%4,%5,%6,%7}, {%8,%9}, {%0,%1,%2,%3};\n"
                        : "+f"(acc[mt][nn][0]), "+f"(acc[mt][nn][1]),
                          "+f"(acc[mt][nn][2]), "+f"(acc[mt][nn][3])
                        : "r"(a0), "r"(a1), "r"(a2), "r"(a3),
                          "r"(b0[nn]), "r"(b1[nn]));
                }
            }
        }

        __syncthreads();   // all reads of sx complete
        if (hasnext) {
#pragma unroll
            for (int it = 0; it < 8; ++it) {
                int idx = tid + it * 256;
                if (idx < XWORDS) {
                    uint32_t h0 = __half_as_ushort(__float2half(quant_fixed(pv0[it])));
                    uint32_t h1 = __half_as_ushort(__float2half(quant_fixed(pv1[it])));
                    sx[idx] = (h1 << 16) | h0;
                }
            }
        }
    }

    // ---- epilogue ----
#pragma unroll
    for (int nn = 0; nn < 4; ++nn) {
        int cl = wn * 32 + nn * 8 + 2 * qc;
        float bq0 = quant_fixed(biasp[cout0 + cl]);
        float bq1 = quant_fixed(biasp[cout0 + cl + 1]);
        float* o0 = out_b + (size_t)(cout0 + cl) * HW;
        float* o1 = o0 + HW;
#pragma unroll
        for (int mt = 0; mt < MTS; ++mt) {
            int mA = (mt0 + mt) * 16 + qr;
            int mB = mA + 8;
            int iA = (oh_base + mA / 56) * W + (mA % 56);
            int iB = (oh_base + mB / 56) * W + (mB % 56);
            o0[iA] = acc[mt][nn][0] + bq0;
            o1[iA] = acc[mt][nn][1] + bq1;
            o0[iB] = acc[mt][nn][2] + bq0;
            o1[iB] = acc[mt][nn][3] + bq1;
        }
    }
}

__global__ __launch_bounds__(256, 2)
void conv_mma_kernel(const float* __restrict__ in,
                     const float* __restrict__ biasp,
                     float* __restrict__ out)
{
    extern __shared__ uint32_t smem[];

    const int tid = threadIdx.x;
    const int w   = tid >> 5;
    const int wm  = w & 1;
    const int wn  = w >> 1;
    const int oh_base = blockIdx.x * 2;
    const int cout0   = blockIdx.y * 128;
    const int b       = blockIdx.z;

    const float* in_b  = in  + (size_t)b * C * HW;
    float*       out_b = out + (size_t)b * COUT * HW;

    if (wm == 0)
        conv_body<4>(in_b, biasp, out_b, smem, oh_base, cout0, tid, wn, 0);
    else
        conv_body<3>(in_b, biasp, out_b, smem, oh_base, cout0, tid, wn, 4);
}

extern "C" void kernel_launch(void* const* d_in, const int* in_sizes, int n_in,
                              void* d_out, int out_size)
{
    const float* in    = (const float*)d_in[0];
    const float* shift = (const float*)d_in[1];
    const float* sign  = (const float*)d_in[2];
    const float* bias  = (const float*)d_in[3];
    float* out = (float*)d_out;

    cudaFuncSetAttribute(conv_mma_kernel,
                         cudaFuncAttributeMaxDynamicSharedMemorySize, SMEM_BYTES);

    quant_weights_kernel<<<2304, 256>>>(shift, sign);
    dim3 grid(H / 2, COUT / 128, BATCH);               // 28 x 2 x 32
    conv_mma_kernel<<<grid, 256, SMEM_BYTES>>>(in, bias, out);
}